// round 1
// baseline (speedup 1.0000x reference)
#include <cuda_runtime.h>
#include <cstdint>

#define N_TOK 8192
#define DMODEL 1024
#define HDIM 4096
#define NEXP 8
#define TOPK 2
#define LN_EPS 1e-5f

#define BM 64
#define BN 128
#define BK 32
#define BKP 36
#define TPB 256

// ---------------- scratch (device globals: allocation-free rule) ----------------
__device__ float g_hbuf[N_TOK * TOPK * HDIM];     // 268 MB: permuted hidden acts
__device__ float g_acc[N_TOK * DMODEL];           // 33 MB: moe output accumulator
__device__ int   g_topk_idx[N_TOK * TOPK];
__device__ float g_topk_w[N_TOK * TOPK];
__device__ int   g_count[NEXP];
__device__ int   g_offset[NEXP];
__device__ int   g_cursor[NEXP];
__device__ int   g_list_token[N_TOK * TOPK];
__device__ float g_list_w[N_TOK * TOPK];

// ---------------- helpers ----------------
__device__ __forceinline__ float tf32r(float f) {
    unsigned int u;
    asm("cvt.rna.tf32.f32 %0, %1;" : "=r"(u) : "f"(f));
    return __uint_as_float(u);
}

__device__ __forceinline__ void mma_tf32(float (&c)[4],
                                         unsigned a0, unsigned a1, unsigned a2, unsigned a3,
                                         unsigned b0, unsigned b1) {
    asm volatile(
        "mma.sync.aligned.m16n8k8.row.col.f32.tf32.tf32.f32 "
        "{%0,%1,%2,%3}, {%4,%5,%6,%7}, {%8,%9}, {%0,%1,%2,%3};"
        : "+f"(c[0]), "+f"(c[1]), "+f"(c[2]), "+f"(c[3])
        : "r"(a0), "r"(a1), "r"(a2), "r"(a3), "r"(b0), "r"(b1));
}

// ---------------- kernel 0: init ----------------
__global__ void init_kernel() {
    int tid = blockIdx.x * blockDim.x + threadIdx.x;
    int nth = gridDim.x * blockDim.x;
    for (int i = tid; i < N_TOK * DMODEL; i += nth) g_acc[i] = 0.f;
    if (blockIdx.x == 0 && threadIdx.x < NEXP) {
        g_count[threadIdx.x] = 0;
        g_cursor[threadIdx.x] = 0;
    }
}

// ---------------- kernel 1: gating (logits, softmax, top2, renorm, counts) ----------------
__global__ void gate_kernel(const float* __restrict__ x, const float* __restrict__ gw,
                            const float* __restrict__ gb) {
    __shared__ float xs[DMODEL];
    __shared__ float lg[NEXP];
    int n = blockIdx.x, tid = threadIdx.x;
    ((float4*)xs)[tid] = ((const float4*)(x + (size_t)n * DMODEL))[tid];
    __syncthreads();
    int w = tid >> 5, lane = tid & 31;
    const float* gr = gw + w * DMODEL;
    float s = 0.f;
    #pragma unroll 8
    for (int j = lane; j < DMODEL; j += 32) s += xs[j] * gr[j];
    #pragma unroll
    for (int o = 16; o; o >>= 1) s += __shfl_xor_sync(0xffffffffu, s, o);
    if (lane == 0) lg[w] = s + gb[w];
    __syncthreads();
    if (tid == 0) {
        float l[NEXP];
        #pragma unroll
        for (int e = 0; e < NEXP; e++) l[e] = lg[e];
        int i1 = 0;
        #pragma unroll
        for (int e = 1; e < NEXP; e++) if (l[e] > l[i1]) i1 = e;
        int i2 = (i1 == 0) ? 1 : 0;
        #pragma unroll
        for (int e = 0; e < NEXP; e++) if (e != i1 && l[e] > l[i2]) i2 = e;
        float m = l[0];
        #pragma unroll
        for (int e = 1; e < NEXP; e++) m = fmaxf(m, l[e]);
        float z = 0.f;
        #pragma unroll
        for (int e = 0; e < NEXP; e++) z += expf(l[e] - m);
        float p1 = expf(l[i1] - m) / z;
        float p2 = expf(l[i2] - m) / z;
        // softmax over the two (descending) probabilities
        float t = expf(p2 - p1);
        float wA = 1.f / (1.f + t);
        float wB = t / (1.f + t);
        g_topk_idx[n * 2 + 0] = i1;
        g_topk_idx[n * 2 + 1] = i2;
        g_topk_w[n * 2 + 0] = wA;
        g_topk_w[n * 2 + 1] = wB;
        atomicAdd(&g_count[i1], 1);
        atomicAdd(&g_count[i2], 1);
    }
}

// ---------------- kernel 2: tiny exclusive scan over E=8 ----------------
__global__ void scan_kernel() {
    if (threadIdx.x == 0) {
        int s = 0;
        for (int e = 0; e < NEXP; e++) { g_offset[e] = s; s += g_count[e]; }
    }
}

// ---------------- kernel 3: scatter tokens into per-expert compact lists ----------------
__global__ void scatter_kernel() {
    int n = blockIdx.x * blockDim.x + threadIdx.x;
    if (n >= N_TOK) return;
    #pragma unroll
    for (int s = 0; s < TOPK; s++) {
        int e = g_topk_idx[n * TOPK + s];
        int pos = atomicAdd(&g_cursor[e], 1);
        int row = g_offset[e] + pos;
        g_list_token[row] = n;
        g_list_w[row] = g_topk_w[n * TOPK + s];
    }
}

// ---------------- kernel 4: grouped GEMM1  H1 = relu(Xperm @ W1e^T + b1e) ----------------
__global__ __launch_bounds__(TPB, 2)
void ffn1_kernel(const float* __restrict__ x, const float* __restrict__ w1,
                 const float* __restrict__ b1v) {
    int e = blockIdx.z;
    int cnt = g_count[e];
    int tile = blockIdx.y;
    if (tile * BM >= cnt) return;
    int rbase = g_offset[e] + tile * BM;
    int nrows = min(cnt - tile * BM, BM);
    int hbase = blockIdx.x * BN;

    extern __shared__ float sm[];
    float (*As)[BM][BKP] = reinterpret_cast<float(*)[BM][BKP]>(sm);
    float (*Bs)[BN][BKP] = reinterpret_cast<float(*)[BN][BKP]>(sm + 2 * BM * BKP);

    int tid = threadIdx.x;
    int warp = tid >> 5, lane = tid & 31;
    int wm = warp & 1, wn = warp >> 1;
    int grp = lane >> 2, tig = lane & 3;

    int arow = tid >> 2;
    int acol = (tid & 3) * 8;
    bool avalid = (arow < nrows);
    const float* aptr = x;
    if (avalid) aptr = x + (size_t)g_list_token[rbase + arow] * DMODEL + acol;

    const float* wbase = w1 + ((size_t)e * HDIM + hbase) * DMODEL;

    float4 areg0, areg1, breg[4];

    auto gload = [&](int k0) {
        if (avalid) {
            areg0 = *(const float4*)(aptr + k0);
            areg1 = *(const float4*)(aptr + k0 + 4);
        } else {
            areg0 = make_float4(0.f, 0.f, 0.f, 0.f);
            areg1 = areg0;
        }
        #pragma unroll
        for (int j = 0; j < 4; j++) {
            int f4 = tid + j * TPB;
            int br = f4 >> 3, bc = (f4 & 7) * 4;
            breg[j] = *(const float4*)(wbase + (size_t)br * DMODEL + k0 + bc);
        }
    };
    auto sstore = [&](int buf) {
        float4 a0 = make_float4(tf32r(areg0.x), tf32r(areg0.y), tf32r(areg0.z), tf32r(areg0.w));
        float4 a1 = make_float4(tf32r(areg1.x), tf32r(areg1.y), tf32r(areg1.z), tf32r(areg1.w));
        *(float4*)&As[buf][arow][acol]     = a0;
        *(float4*)&As[buf][arow][acol + 4] = a1;
        #pragma unroll
        for (int j = 0; j < 4; j++) {
            int f4 = tid + j * TPB;
            int br = f4 >> 3, bc = (f4 & 7) * 4;
            float4 b = make_float4(tf32r(breg[j].x), tf32r(breg[j].y), tf32r(breg[j].z), tf32r(breg[j].w));
            *(float4*)&Bs[buf][br][bc] = b;
        }
    };

    float acc[2][4][4];
    #pragma unroll
    for (int mi = 0; mi < 2; mi++)
        #pragma unroll
        for (int ni = 0; ni < 4; ni++)
            #pragma unroll
            for (int q = 0; q < 4; q++) acc[mi][ni][q] = 0.f;

    auto compute = [&](int buf) {
        #pragma unroll
        for (int ks = 0; ks < BK / 8; ks++) {
            int k8 = ks * 8;
            unsigned af[2][4], bfr[4][2];
            #pragma unroll
            for (int mi = 0; mi < 2; mi++) {
                int rb = wm * 32 + mi * 16;
                af[mi][0] = __float_as_uint(As[buf][rb + grp    ][k8 + tig    ]);
                af[mi][1] = __float_as_uint(As[buf][rb + grp + 8][k8 + tig    ]);
                af[mi][2] = __float_as_uint(As[buf][rb + grp    ][k8 + tig + 4]);
                af[mi][3] = __float_as_uint(As[buf][rb + grp + 8][k8 + tig + 4]);
            }
            #pragma unroll
            for (int ni = 0; ni < 4; ni++) {
                int nb = wn * 32 + ni * 8 + grp;
                bfr[ni][0] = __float_as_uint(Bs[buf][nb][k8 + tig    ]);
                bfr[ni][1] = __float_as_uint(Bs[buf][nb][k8 + tig + 4]);
            }
            #pragma unroll
            for (int mi = 0; mi < 2; mi++)
                #pragma unroll
                for (int ni = 0; ni < 4; ni++)
                    mma_tf32(acc[mi][ni], af[mi][0], af[mi][1], af[mi][2], af[mi][3],
                             bfr[ni][0], bfr[ni][1]);
        }
    };

    gload(0); sstore(0); __syncthreads();
    const int NIT = DMODEL / BK;
    for (int it = 0; it < NIT; it++) {
        int buf = it & 1;
        if (it + 1 < NIT) gload((it + 1) * BK);
        compute(buf);
        if (it + 1 < NIT) { sstore(buf ^ 1); __syncthreads(); }
    }

    #pragma unroll
    for (int mi = 0; mi < 2; mi++) {
        #pragma unroll
        for (int half = 0; half < 2; half++) {
            int r = wm * 32 + mi * 16 + grp + half * 8;
            if (r < nrows) {
                size_t orow = (size_t)(rbase + r) * HDIM;
                #pragma unroll
                for (int ni = 0; ni < 4; ni++) {
                    int c = hbase + wn * 32 + ni * 8 + 2 * tig;
                    float v0 = fmaxf(acc[mi][ni][half * 2 + 0] + b1v[e * HDIM + c], 0.f);
                    float v1 = fmaxf(acc[mi][ni][half * 2 + 1] + b1v[e * HDIM + c + 1], 0.f);
                    *(float2*)&g_hbuf[orow + c] = make_float2(v0, v1);
                }
            }
        }
    }
}

// ---------------- kernel 5: grouped GEMM2  acc += wgt * (H1 @ W2e^T + b2e) ----------------
__global__ __launch_bounds__(TPB, 2)
void ffn2_kernel(const float* __restrict__ w2, const float* __restrict__ b2v) {
    int e = blockIdx.z;
    int cnt = g_count[e];
    int tile = blockIdx.y;
    if (tile * BM >= cnt) return;
    int rbase = g_offset[e] + tile * BM;
    int nrows = min(cnt - tile * BM, BM);
    int dbase = blockIdx.x * BN;

    extern __shared__ float sm[];
    float (*As)[BM][BKP] = reinterpret_cast<float(*)[BM][BKP]>(sm);
    float (*Bs)[BN][BKP] = reinterpret_cast<float(*)[BN][BKP]>(sm + 2 * BM * BKP);

    int tid = threadIdx.x;
    int warp = tid >> 5, lane = tid & 31;
    int wm = warp & 1, wn = warp >> 1;
    int grp = lane >> 2, tig = lane & 3;

    int arow = tid >> 2;
    int acol = (tid & 3) * 8;
    bool avalid = (arow < nrows);
    const float* aptr = g_hbuf;
    if (avalid) aptr = g_hbuf + (size_t)(rbase + arow) * HDIM + acol;

    const float* wbase = w2 + ((size_t)e * DMODEL + dbase) * HDIM;

    float4 areg0, areg1, breg[4];

    auto gload = [&](int k0) {
        if (avalid) {
            areg0 = *(const float4*)(aptr + k0);
            areg1 = *(const float4*)(aptr + k0 + 4);
        } else {
            areg0 = make_float4(0.f, 0.f, 0.f, 0.f);
            areg1 = areg0;
        }
        #pragma unroll
        for (int j = 0; j < 4; j++) {
            int f4 = tid + j * TPB;
            int br = f4 >> 3, bc = (f4 & 7) * 4;
            breg[j] = *(const float4*)(wbase + (size_t)br * HDIM + k0 + bc);
        }
    };
    auto sstore = [&](int buf) {
        float4 a0 = make_float4(tf32r(areg0.x), tf32r(areg0.y), tf32r(areg0.z), tf32r(areg0.w));
        float4 a1 = make_float4(tf32r(areg1.x), tf32r(areg1.y), tf32r(areg1.z), tf32r(areg1.w));
        *(float4*)&As[buf][arow][acol]     = a0;
        *(float4*)&As[buf][arow][acol + 4] = a1;
        #pragma unroll
        for (int j = 0; j < 4; j++) {
            int f4 = tid + j * TPB;
            int br = f4 >> 3, bc = (f4 & 7) * 4;
            float4 b = make_float4(tf32r(breg[j].x), tf32r(breg[j].y), tf32r(breg[j].z), tf32r(breg[j].w));
            *(float4*)&Bs[buf][br][bc] = b;
        }
    };

    float acc[2][4][4];
    #pragma unroll
    for (int mi = 0; mi < 2; mi++)
        #pragma unroll
        for (int ni = 0; ni < 4; ni++)
            #pragma unroll
            for (int q = 0; q < 4; q++) acc[mi][ni][q] = 0.f;

    auto compute = [&](int buf) {
        #pragma unroll
        for (int ks = 0; ks < BK / 8; ks++) {
            int k8 = ks * 8;
            unsigned af[2][4], bfr[4][2];
            #pragma unroll
            for (int mi = 0; mi < 2; mi++) {
                int rb = wm * 32 + mi * 16;
                af[mi][0] = __float_as_uint(As[buf][rb + grp    ][k8 + tig    ]);
                af[mi][1] = __float_as_uint(As[buf][rb + grp + 8][k8 + tig    ]);
                af[mi][2] = __float_as_uint(As[buf][rb + grp    ][k8 + tig + 4]);
                af[mi][3] = __float_as_uint(As[buf][rb + grp + 8][k8 + tig + 4]);
            }
            #pragma unroll
            for (int ni = 0; ni < 4; ni++) {
                int nb = wn * 32 + ni * 8 + grp;
                bfr[ni][0] = __float_as_uint(Bs[buf][nb][k8 + tig    ]);
                bfr[ni][1] = __float_as_uint(Bs[buf][nb][k8 + tig + 4]);
            }
            #pragma unroll
            for (int mi = 0; mi < 2; mi++)
                #pragma unroll
                for (int ni = 0; ni < 4; ni++)
                    mma_tf32(acc[mi][ni], af[mi][0], af[mi][1], af[mi][2], af[mi][3],
                             bfr[ni][0], bfr[ni][1]);
        }
    };

    gload(0); sstore(0); __syncthreads();
    const int NIT = HDIM / BK;
    for (int it = 0; it < NIT; it++) {
        int buf = it & 1;
        if (it + 1 < NIT) gload((it + 1) * BK);
        compute(buf);
        if (it + 1 < NIT) { sstore(buf ^ 1); __syncthreads(); }
    }

    #pragma unroll
    for (int mi = 0; mi < 2; mi++) {
        #pragma unroll
        for (int half = 0; half < 2; half++) {
            int r = wm * 32 + mi * 16 + grp + half * 8;
            if (r < nrows) {
                int tok = g_list_token[rbase + r];
                float wgt = g_list_w[rbase + r];
                float* outrow = g_acc + (size_t)tok * DMODEL;
                #pragma unroll
                for (int ni = 0; ni < 4; ni++) {
                    int c = dbase + wn * 32 + ni * 8 + 2 * tig;
                    float v0 = (acc[mi][ni][half * 2 + 0] + b2v[e * DMODEL + c]) * wgt;
                    float v1 = (acc[mi][ni][half * 2 + 1] + b2v[e * DMODEL + c + 1]) * wgt;
                    atomicAdd(outrow + c, v0);
                    atomicAdd(outrow + c + 1, v1);
                }
            }
        }
    }
}

// ---------------- kernel 6: residual + LayerNorm ----------------
__device__ __forceinline__ float block_sum(float v, float* red) {
    __syncthreads();
    #pragma unroll
    for (int o = 16; o; o >>= 1) v += __shfl_xor_sync(0xffffffffu, v, o);
    int w = threadIdx.x >> 5, lane = threadIdx.x & 31;
    if (lane == 0) red[w] = v;
    __syncthreads();
    if (w == 0) {
        v = (lane < 8) ? red[lane] : 0.f;
        #pragma unroll
        for (int o = 4; o; o >>= 1) v += __shfl_xor_sync(0xffffffffu, v, o);
        if (lane == 0) red[0] = v;
    }
    __syncthreads();
    return red[0];
}

__global__ void ln_kernel(const float* __restrict__ x, const float* __restrict__ lnw,
                          const float* __restrict__ lnb, float* __restrict__ out) {
    __shared__ float red[32];
    int n = blockIdx.x, tid = threadIdx.x;
    float4 xv = ((const float4*)(x + (size_t)n * DMODEL))[tid];
    float4 av = ((const float4*)(g_acc + (size_t)n * DMODEL))[tid];
    float rx = xv.x + av.x, ry = xv.y + av.y, rz = xv.z + av.z, rw = xv.w + av.w;
    float s = block_sum(rx + ry + rz + rw, red);
    float mu = s * (1.f / DMODEL);
    float dx = rx - mu, dy = ry - mu, dz = rz - mu, dw = rw - mu;
    float sq = block_sum(dx * dx + dy * dy + dz * dz + dw * dw, red);
    float inv = rsqrtf(sq * (1.f / DMODEL) + LN_EPS);
    float4 wv = ((const float4*)lnw)[tid];
    float4 bv = ((const float4*)lnb)[tid];
    float4 o = make_float4(dx * inv * wv.x + bv.x, dy * inv * wv.y + bv.y,
                           dz * inv * wv.z + bv.z, dw * inv * wv.w + bv.w);
    ((float4*)(out + (size_t)n * DMODEL))[tid] = o;
}

// ---------------- launch ----------------
extern "C" void kernel_launch(void* const* d_in, const int* in_sizes, int n_in,
                              void* d_out, int out_size) {
    const float* x   = (const float*)d_in[0];
    const float* gw  = (const float*)d_in[1];
    const float* gb  = (const float*)d_in[2];
    const float* w1  = (const float*)d_in[3];
    const float* b1  = (const float*)d_in[4];
    const float* w2  = (const float*)d_in[5];
    const float* b2  = (const float*)d_in[6];
    const float* lnw = (const float*)d_in[7];
    const float* lnb = (const float*)d_in[8];
    float* out = (float*)d_out;

    const int SMEM = 2 * (BM + BN) * BKP * 4;  // 55296 bytes
    cudaFuncSetAttribute(ffn1_kernel, cudaFuncAttributeMaxDynamicSharedMemorySize, SMEM);
    cudaFuncSetAttribute(ffn2_kernel, cudaFuncAttributeMaxDynamicSharedMemorySize, SMEM);

    init_kernel<<<1024, 256>>>();
    gate_kernel<<<N_TOK, 256>>>(x, gw, gb);
    scan_kernel<<<1, 32>>>();
    scatter_kernel<<<(N_TOK + 255) / 256, 256>>>();
    ffn1_kernel<<<dim3(HDIM / BN, (N_TOK + BM - 1) / BM, NEXP), TPB, SMEM>>>(x, w1, b1);
    ffn2_kernel<<<dim3(DMODEL / BN, (N_TOK + BM - 1) / BM, NEXP), TPB, SMEM>>>(w2, b2);
    ln_kernel<<<N_TOK, 256>>>(x, lnw, lnb, out);
}

// round 3
// speedup vs baseline: 2.3878x; 2.3878x over previous
#include <cuda_runtime.h>
#include <cuda_fp16.h>
#include <cstdint>

#define N_TOK 8192
#define DMODEL 1024
#define HDIM 4096
#define NEXP 8
#define LN_EPS 1e-5f
#define TOTALR (N_TOK * 2)

#define TILE_M 128
#define TILE_N 256
#define BK 32
#define STAGES 4
#define A_BYTES 8192            /* 128 rows * 64 B */
#define B_BYTES 16384           /* 256 rows * 64 B */
#define STAGE_BYTES 24576
#define SMEM_DYN (STAGES * STAGE_BYTES)   /* 98304 */
#define MAX_TILES 136

// ---------------- scratch ----------------
__device__ __half g_w1h[(size_t)NEXP * HDIM * DMODEL];   // 67 MB
__device__ __half g_w2h[(size_t)NEXP * DMODEL * HDIM];   // 67 MB
__device__ __half g_xh[(size_t)N_TOK * DMODEL];          // 16 MB
__device__ __half g_h16[(size_t)TOTALR * HDIM];          // 134 MB
__device__ float  g_ybuf[(size_t)TOTALR * DMODEL];       // 67 MB
__device__ int    g_topk_idx[TOTALR];
__device__ float  g_topk_w[TOTALR];
__device__ int    g_count[NEXP];
__device__ int    g_offset[NEXP];
__device__ int    g_cursor[NEXP];
__device__ int    g_list_token[TOTALR];
__device__ float  g_list_w[TOTALR];
__device__ int    g_pos[TOTALR];
__device__ int    g_tile_rbase[MAX_TILES];
__device__ int    g_tile_rows[MAX_TILES];
__device__ int    g_tile_e[MAX_TILES];
__device__ int    g_n_tiles;

// ---------------- PTX helpers ----------------
__device__ __forceinline__ uint32_t smem_u32(const void* p) {
    uint32_t a;
    asm("{ .reg .u64 t; cvta.to.shared.u64 t, %1; cvt.u32.u64 %0, t; }" : "=r"(a) : "l"(p));
    return a;
}

#define CP_ASYNC16(dst, src) \
    asm volatile("cp.async.cg.shared.global [%0], [%1], 16;" :: "r"((uint32_t)(dst)), "l"(src) : "memory")
#define CP_COMMIT() asm volatile("cp.async.commit_group;" ::: "memory")
#define CP_WAIT(n)  asm volatile("cp.async.wait_group %0;" :: "n"(n) : "memory")

#define LDSM_X4(r0, r1, r2, r3, addr) \
    asm volatile("ldmatrix.sync.aligned.m8n8.x4.shared.b16 {%0,%1,%2,%3}, [%4];" \
        : "=r"(r0), "=r"(r1), "=r"(r2), "=r"(r3) : "r"(addr))

#define MMA16816(c, a0, a1, a2, a3, b0, b1) \
    asm volatile("mma.sync.aligned.m16n8k16.row.col.f32.f16.f16.f32 " \
        "{%0,%1,%2,%3}, {%4,%5,%6,%7}, {%8,%9}, {%0,%1,%2,%3};" \
        : "+f"((c)[0]), "+f"((c)[1]), "+f"((c)[2]), "+f"((c)[3]) \
        : "r"(a0), "r"(a1), "r"(a2), "r"(a3), "r"(b0), "r"(b1))

// ---------------- kernel: fp32 -> fp16 convert ----------------
__global__ void cvt_kernel(const float* __restrict__ src, __half* __restrict__ dst, int n4) {
    int i = blockIdx.x * blockDim.x + threadIdx.x;
    int nth = gridDim.x * blockDim.x;
    for (; i < n4; i += nth) {
        float4 v = ((const float4*)src)[i];
        ((__half2*)dst)[2 * i]     = __floats2half2_rn(v.x, v.y);
        ((__half2*)dst)[2 * i + 1] = __floats2half2_rn(v.z, v.w);
    }
}

// ---------------- kernel: init ----------------
__global__ void init_kernel() {
    if (threadIdx.x < NEXP) { g_count[threadIdx.x] = 0; g_cursor[threadIdx.x] = 0; }
}

// ---------------- kernel: gating ----------------
__global__ void gate_kernel(const float* __restrict__ x, const float* __restrict__ gw,
                            const float* __restrict__ gb) {
    __shared__ float xs[DMODEL];
    __shared__ float lg[NEXP];
    int n = blockIdx.x, tid = threadIdx.x;
    ((float4*)xs)[tid] = ((const float4*)(x + (size_t)n * DMODEL))[tid];
    __syncthreads();
    int w = tid >> 5, lane = tid & 31;
    const float* gr = gw + w * DMODEL;
    float s = 0.f;
    #pragma unroll 8
    for (int j = lane; j < DMODEL; j += 32) s += xs[j] * gr[j];
    #pragma unroll
    for (int o = 16; o; o >>= 1) s += __shfl_xor_sync(0xffffffffu, s, o);
    if (lane == 0) lg[w] = s + gb[w];
    __syncthreads();
    if (tid == 0) {
        float l[NEXP];
        #pragma unroll
        for (int e = 0; e < NEXP; e++) l[e] = lg[e];
        int i1 = 0;
        #pragma unroll
        for (int e = 1; e < NEXP; e++) if (l[e] > l[i1]) i1 = e;
        int i2 = (i1 == 0) ? 1 : 0;
        #pragma unroll
        for (int e = 0; e < NEXP; e++) if (e != i1 && l[e] > l[i2]) i2 = e;
        float m = l[0];
        #pragma unroll
        for (int e = 1; e < NEXP; e++) m = fmaxf(m, l[e]);
        float z = 0.f;
        #pragma unroll
        for (int e = 0; e < NEXP; e++) z += expf(l[e] - m);
        float p1 = expf(l[i1] - m) / z;
        float p2 = expf(l[i2] - m) / z;
        float t = expf(p2 - p1);
        g_topk_idx[n * 2 + 0] = i1;
        g_topk_idx[n * 2 + 1] = i2;
        g_topk_w[n * 2 + 0] = 1.f / (1.f + t);
        g_topk_w[n * 2 + 1] = t / (1.f + t);
        atomicAdd(&g_count[i1], 1);
        atomicAdd(&g_count[i2], 1);
    }
}

// ---------------- kernel: scan + tile table ----------------
__global__ void scan_kernel() {
    if (threadIdx.x == 0) {
        int s = 0, nt = 0;
        for (int e = 0; e < NEXP; e++) {
            g_offset[e] = s;
            int c = g_count[e];
            for (int i = 0; i < c; i += TILE_M) {
                g_tile_rbase[nt] = s + i;
                g_tile_rows[nt] = min(c - i, TILE_M);
                g_tile_e[nt] = e;
                nt++;
            }
            s += c;
        }
        g_n_tiles = nt;
    }
}

// ---------------- kernel: scatter ----------------
__global__ void scatter_kernel() {
    int n = blockIdx.x * blockDim.x + threadIdx.x;
    if (n >= N_TOK) return;
    #pragma unroll
    for (int s = 0; s < 2; s++) {
        int e = g_topk_idx[n * 2 + s];
        int pos = atomicAdd(&g_cursor[e], 1);
        int row = g_offset[e] + pos;
        g_list_token[row] = n;
        g_list_w[row] = g_topk_w[n * 2 + s];
        g_pos[n * 2 + s] = row;
    }
}

// ---------------- fp16 mma.sync grouped GEMM ----------------
// PHASE 1: h = relu(Xg @ W1e^T + b1e)   (KD=1024, NOUT=4096)
// PHASE 2: y = (H  @ W2e^T + b2e) * wgt (KD=4096, NOUT=1024)
template <int KD, int NOUT, int PHASE>
__global__ __launch_bounds__(256, 1)
void ffn_kernel(const __half* __restrict__ W, const float* __restrict__ bias) {
    int tile = blockIdx.x;
    if (tile >= g_n_tiles) return;
    int e = g_tile_e[tile];
    int rbase = g_tile_rbase[tile];
    int nrows = g_tile_rows[tile];
    int nbase = blockIdx.y * TILE_N;
    constexpr int T = KD / BK;

    extern __shared__ __align__(1024) char smem[];
    uint32_t sbase = smem_u32(smem);

    int tid = threadIdx.x;
    int lane = tid & 31, wid = tid >> 5;
    int warp_m = wid & 1, warp_n = wid >> 1;

    // ---- producer src/dst precompute (2 A chunks + 4 B chunks of 16B per thread) ----
    uint32_t adst[2];
    const char* asrc[2];
    #pragma unroll
    for (int j = 0; j < 2; j++) {
        int g = tid + j * 256;
        int r = g >> 2, c = g & 3;
        adst[j] = (uint32_t)(r * 64 + ((c ^ ((r >> 1) & 3)) << 4));
        int rl = (r < nrows) ? r : (nrows - 1);
        int idx = rbase + rl;
        const __half* ap;
        if (PHASE == 1) ap = g_xh + (size_t)g_list_token[idx] * DMODEL;
        else            ap = g_h16 + (size_t)idx * HDIM;
        asrc[j] = (const char*)ap + c * 16;
    }
    uint32_t bdst[4];
    const char* bsrc[4];
    #pragma unroll
    for (int j = 0; j < 4; j++) {
        int g = tid + j * 256;
        int r = g >> 2, c = g & 3;
        bdst[j] = (uint32_t)(A_BYTES + r * 64 + ((c ^ ((r >> 1) & 3)) << 4));
        bsrc[j] = (const char*)(W + ((size_t)e * NOUT + nbase + r) * KD) + c * 16;
    }

    auto issue_tile = [&](int t) {
        uint32_t sb = sbase + (t % STAGES) * STAGE_BYTES;
        size_t koff = (size_t)t * 64;
        #pragma unroll
        for (int j = 0; j < 2; j++) CP_ASYNC16(sb + adst[j], asrc[j] + koff);
        #pragma unroll
        for (int j = 0; j < 4; j++) CP_ASYNC16(sb + bdst[j], bsrc[j] + koff);
    };

    // ---- ldmatrix address precompute ----
    int a_row = warp_m * 64 + (lane & 15);
    int a_hi = (lane >> 4) & 1;
    int a_sw = (a_row >> 1) & 3;
    uint32_t a_base = (uint32_t)(a_row * 64);
    int b_row = warp_n * 64 + (lane & 7) + ((lane & 16) ? 8 : 0);
    int b_hi = (lane >> 3) & 1;
    int b_sw = (b_row >> 1) & 3;
    uint32_t b_base = (uint32_t)(A_BYTES + b_row * 64);

    float acc[4][8][4];
    #pragma unroll
    for (int mi = 0; mi < 4; mi++)
        #pragma unroll
        for (int ni = 0; ni < 8; ni++)
            #pragma unroll
            for (int q = 0; q < 4; q++) acc[mi][ni][q] = 0.f;

    // ---- prologue ----
    #pragma unroll
    for (int t = 0; t < STAGES - 1; t++) { issue_tile(t); CP_COMMIT(); }

    // ---- mainloop ----
    for (int t = 0; t < T; t++) {
        CP_WAIT(STAGES - 2);
        __syncthreads();
        uint32_t sb = sbase + (t % STAGES) * STAGE_BYTES;
        #pragma unroll
        for (int ks = 0; ks < 2; ks++) {
            uint32_t ach = (uint32_t)(((ks * 2 + a_hi) ^ a_sw) << 4);
            uint32_t bch = (uint32_t)(((ks * 2 + b_hi) ^ b_sw) << 4);
            uint32_t a[4][4], b[4][4];
            #pragma unroll
            for (int mi = 0; mi < 4; mi++)
                LDSM_X4(a[mi][0], a[mi][1], a[mi][2], a[mi][3], sb + a_base + mi * 1024 + ach);
            #pragma unroll
            for (int ni = 0; ni < 4; ni++)
                LDSM_X4(b[ni][0], b[ni][1], b[ni][2], b[ni][3], sb + b_base + ni * 1024 + bch);
            #pragma unroll
            for (int mi = 0; mi < 4; mi++)
                #pragma unroll
                for (int ni = 0; ni < 4; ni++) {
                    MMA16816(acc[mi][2 * ni],     a[mi][0], a[mi][1], a[mi][2], a[mi][3],
                             b[ni][0], b[ni][1]);
                    MMA16816(acc[mi][2 * ni + 1], a[mi][0], a[mi][1], a[mi][2], a[mi][3],
                             b[ni][2], b[ni][3]);
                }
        }
        __syncthreads();
        if (t + STAGES - 1 < T) issue_tile(t + STAGES - 1);
        CP_COMMIT();
    }

    // ---- epilogue ----
    int r0 = warp_m * 64 + (lane >> 2);
    int cql = (lane & 3) * 2;
    #pragma unroll
    for (int mi = 0; mi < 4; mi++) {
        #pragma unroll
        for (int half = 0; half < 2; half++) {
            int r = r0 + mi * 16 + half * 8;
            if (r < nrows) {
                int rglob = rbase + r;
                if (PHASE == 1) {
                    __half* hp = g_h16 + (size_t)rglob * HDIM + nbase + warp_n * 64 + cql;
                    const float* bp = bias + (size_t)e * NOUT + nbase + warp_n * 64 + cql;
                    #pragma unroll
                    for (int n8 = 0; n8 < 8; n8++) {
                        float v0 = fmaxf(acc[mi][n8][half * 2 + 0] + bp[n8 * 8], 0.f);
                        float v1 = fmaxf(acc[mi][n8][half * 2 + 1] + bp[n8 * 8 + 1], 0.f);
                        *(__half2*)(hp + n8 * 8) = __floats2half2_rn(v0, v1);
                    }
                } else {
                    float wgt = g_list_w[rglob];
                    float* yp = g_ybuf + (size_t)rglob * DMODEL + nbase + warp_n * 64 + cql;
                    const float* bp = bias + (size_t)e * NOUT + nbase + warp_n * 64 + cql;
                    #pragma unroll
                    for (int n8 = 0; n8 < 8; n8++) {
                        float v0 = (acc[mi][n8][half * 2 + 0] + bp[n8 * 8]) * wgt;
                        float v1 = (acc[mi][n8][half * 2 + 1] + bp[n8 * 8 + 1]) * wgt;
                        *(float2*)(yp + n8 * 8) = make_float2(v0, v1);
                    }
                }
            }
        }
    }
}

// ---------------- kernel: residual + LayerNorm ----------------
__device__ __forceinline__ float block_sum(float v, float* red) {
    __syncthreads();
    #pragma unroll
    for (int o = 16; o; o >>= 1) v += __shfl_xor_sync(0xffffffffu, v, o);
    int w = threadIdx.x >> 5, lane = threadIdx.x & 31;
    if (lane == 0) red[w] = v;
    __syncthreads();
    if (w == 0) {
        v = (lane < 8) ? red[lane] : 0.f;
        #pragma unroll
        for (int o = 4; o; o >>= 1) v += __shfl_xor_sync(0xffffffffu, v, o);
        if (lane == 0) red[0] = v;
    }
    __syncthreads();
    return red[0];
}

__global__ void ln_kernel(const float* __restrict__ x, const float* __restrict__ lnw,
                          const float* __restrict__ lnb, float* __restrict__ out) {
    __shared__ float red[32];
    int n = blockIdx.x, tid = threadIdx.x;
    int p0 = g_pos[n * 2 + 0];
    int p1 = g_pos[n * 2 + 1];
    float4 xv = ((const float4*)(x + (size_t)n * DMODEL))[tid];
    float4 a0 = ((const float4*)(&g_ybuf[(size_t)p0 * DMODEL]))[tid];
    float4 a1 = ((const float4*)(&g_ybuf[(size_t)p1 * DMODEL]))[tid];
    float rx = xv.x + a0.x + a1.x, ry = xv.y + a0.y + a1.y;
    float rz = xv.z + a0.z + a1.z, rw = xv.w + a0.w + a1.w;
    float s = block_sum(rx + ry + rz + rw, red);
    float mu = s * (1.f / DMODEL);
    float dx = rx - mu, dy = ry - mu, dz = rz - mu, dw = rw - mu;
    float sq = block_sum(dx * dx + dy * dy + dz * dz + dw * dw, red);
    float inv = rsqrtf(sq * (1.f / DMODEL) + LN_EPS);
    float4 wv = ((const float4*)lnw)[tid];
    float4 bv = ((const float4*)lnb)[tid];
    float4 o = make_float4(dx * inv * wv.x + bv.x, dy * inv * wv.y + bv.y,
                           dz * inv * wv.z + bv.z, dw * inv * wv.w + bv.w);
    ((float4*)(out + (size_t)n * DMODEL))[tid] = o;
}

// ---------------- launch ----------------
extern "C" void kernel_launch(void* const* d_in, const int* in_sizes, int n_in,
                              void* d_out, int out_size) {
    const float* x   = (const float*)d_in[0];
    const float* gw  = (const float*)d_in[1];
    const float* gb  = (const float*)d_in[2];
    const float* w1  = (const float*)d_in[3];
    const float* b1  = (const float*)d_in[4];
    const float* w2  = (const float*)d_in[5];
    const float* b2  = (const float*)d_in[6];
    const float* lnw = (const float*)d_in[7];
    const float* lnb = (const float*)d_in[8];
    float* out = (float*)d_out;

    __half* w1h; cudaGetSymbolAddress((void**)&w1h, g_w1h);
    __half* w2h; cudaGetSymbolAddress((void**)&w2h, g_w2h);
    __half* xh;  cudaGetSymbolAddress((void**)&xh, g_xh);

    cudaFuncSetAttribute(ffn_kernel<DMODEL, HDIM, 1>,
                         cudaFuncAttributeMaxDynamicSharedMemorySize, SMEM_DYN);
    cudaFuncSetAttribute(ffn_kernel<HDIM, DMODEL, 2>,
                         cudaFuncAttributeMaxDynamicSharedMemorySize, SMEM_DYN);

    init_kernel<<<1, 32>>>();
    cvt_kernel<<<2048, 256>>>(w1, w1h, NEXP * HDIM * DMODEL / 4);
    cvt_kernel<<<2048, 256>>>(w2, w2h, NEXP * DMODEL * HDIM / 4);
    cvt_kernel<<<1024, 256>>>(x, xh, N_TOK * DMODEL / 4);
    gate_kernel<<<N_TOK, 256>>>(x, gw, gb);
    scan_kernel<<<1, 32>>>();
    scatter_kernel<<<(N_TOK + 255) / 256, 256>>>();
    ffn_kernel<DMODEL, HDIM, 1><<<dim3(MAX_TILES, HDIM / TILE_N), 256, SMEM_DYN>>>(w1h, b1);
    ffn_kernel<HDIM, DMODEL, 2><<<dim3(MAX_TILES, DMODEL / TILE_N), 256, SMEM_DYN>>>(w2h, b2);
    ln_kernel<<<N_TOK, 256>>>(x, lnw, lnb, out);
}

// round 4
// speedup vs baseline: 2.4264x; 1.0162x over previous
#include <cuda_runtime.h>
#include <cuda_fp16.h>
#include <cstdint>

#define N_TOK 8192
#define DMODEL 1024
#define HDIM 4096
#define NEXP 8
#define LN_EPS 1e-5f
#define TOTALR (N_TOK * 2)

#define TILE_M 128
#define TILE_N 256
#define BK 32
#define STAGES 5
#define A_BYTES 8192            /* 128 rows * 64 B */
#define STAGE_BYTES 24576
#define SMEM_DYN (STAGES * STAGE_BYTES)   /* 122880 */
#define MAX_TILES 136

// ---------------- scratch ----------------
__device__ __half g_w1h[(size_t)NEXP * HDIM * DMODEL];   // 67 MB
__device__ __half g_w2h[(size_t)NEXP * DMODEL * HDIM];   // 67 MB
__device__ __half g_xh[(size_t)N_TOK * DMODEL];          // 16 MB
__device__ __half g_h16[(size_t)TOTALR * HDIM];          // 134 MB
__device__ float  g_ybuf[(size_t)TOTALR * DMODEL];       // 67 MB
__device__ int    g_topk_idx[TOTALR];
__device__ float  g_topk_w[TOTALR];
__device__ int    g_count[NEXP];
__device__ int    g_offset[NEXP];
__device__ int    g_cursor[NEXP];
__device__ int    g_list_token[TOTALR];
__device__ float  g_list_w[TOTALR];
__device__ int    g_pos[TOTALR];
__device__ int    g_tile_rbase[MAX_TILES];
__device__ int    g_tile_rows[MAX_TILES];
__device__ int    g_tile_e[MAX_TILES];
__device__ int    g_n_tiles;

// ---------------- PTX helpers ----------------
__device__ __forceinline__ uint32_t smem_u32(const void* p) {
    uint32_t a;
    asm("{ .reg .u64 t; cvta.to.shared.u64 t, %1; cvt.u32.u64 %0, t; }" : "=r"(a) : "l"(p));
    return a;
}

#define CP_ASYNC16(dst, src) \
    asm volatile("cp.async.cg.shared.global [%0], [%1], 16;" :: "r"((uint32_t)(dst)), "l"(src) : "memory")
#define CP_COMMIT() asm volatile("cp.async.commit_group;" ::: "memory")
#define CP_WAIT(n)  asm volatile("cp.async.wait_group %0;" :: "n"(n) : "memory")

#define LDSM_X4(r0, r1, r2, r3, addr) \
    asm volatile("ldmatrix.sync.aligned.m8n8.x4.shared.b16 {%0,%1,%2,%3}, [%4];" \
        : "=r"(r0), "=r"(r1), "=r"(r2), "=r"(r3) : "r"(addr))

#define MMA16816(c, a0, a1, a2, a3, b0, b1) \
    asm volatile("mma.sync.aligned.m16n8k16.row.col.f32.f16.f16.f32 " \
        "{%0,%1,%2,%3}, {%4,%5,%6,%7}, {%8,%9}, {%0,%1,%2,%3};" \
        : "+f"((c)[0]), "+f"((c)[1]), "+f"((c)[2]), "+f"((c)[3]) \
        : "r"(a0), "r"(a1), "r"(a2), "r"(a3), "r"(b0), "r"(b1))

// ---------------- kernel: fused fp32 -> fp16 weight convert + init ----------------
__global__ void cvtw_kernel(const float* __restrict__ w1, const float* __restrict__ w2) {
    if (blockIdx.x == 0 && threadIdx.x < NEXP) {
        g_count[threadIdx.x] = 0;
        g_cursor[threadIdx.x] = 0;
    }
    const int n4 = NEXP * HDIM * DMODEL / 4;    // per weight tensor
    int i = blockIdx.x * blockDim.x + threadIdx.x;
    int nth = gridDim.x * blockDim.x;
    for (; i < n4; i += nth) {
        float4 v = ((const float4*)w1)[i];
        ((__half2*)g_w1h)[2 * i]     = __floats2half2_rn(v.x, v.y);
        ((__half2*)g_w1h)[2 * i + 1] = __floats2half2_rn(v.z, v.w);
        float4 u = ((const float4*)w2)[i];
        ((__half2*)g_w2h)[2 * i]     = __floats2half2_rn(u.x, u.y);
        ((__half2*)g_w2h)[2 * i + 1] = __floats2half2_rn(u.z, u.w);
    }
}

__global__ void cvtx_kernel(const float* __restrict__ src) {
    int i = blockIdx.x * blockDim.x + threadIdx.x;
    int nth = gridDim.x * blockDim.x;
    for (; i < N_TOK * DMODEL / 4; i += nth) {
        float4 v = ((const float4*)src)[i];
        ((__half2*)g_xh)[2 * i]     = __floats2half2_rn(v.x, v.y);
        ((__half2*)g_xh)[2 * i + 1] = __floats2half2_rn(v.z, v.w);
    }
}

// ---------------- kernel: gating ----------------
__global__ void gate_kernel(const float* __restrict__ x, const float* __restrict__ gw,
                            const float* __restrict__ gb) {
    __shared__ float xs[DMODEL];
    __shared__ float lg[NEXP];
    int n = blockIdx.x, tid = threadIdx.x;
    ((float4*)xs)[tid] = ((const float4*)(x + (size_t)n * DMODEL))[tid];
    __syncthreads();
    int w = tid >> 5, lane = tid & 31;
    const float* gr = gw + w * DMODEL;
    float s = 0.f;
    #pragma unroll 8
    for (int j = lane; j < DMODEL; j += 32) s += xs[j] * gr[j];
    #pragma unroll
    for (int o = 16; o; o >>= 1) s += __shfl_xor_sync(0xffffffffu, s, o);
    if (lane == 0) lg[w] = s + gb[w];
    __syncthreads();
    if (tid == 0) {
        float l[NEXP];
        #pragma unroll
        for (int e = 0; e < NEXP; e++) l[e] = lg[e];
        int i1 = 0;
        #pragma unroll
        for (int e = 1; e < NEXP; e++) if (l[e] > l[i1]) i1 = e;
        int i2 = (i1 == 0) ? 1 : 0;
        #pragma unroll
        for (int e = 0; e < NEXP; e++) if (e != i1 && l[e] > l[i2]) i2 = e;
        float m = l[0];
        #pragma unroll
        for (int e = 1; e < NEXP; e++) m = fmaxf(m, l[e]);
        float z = 0.f;
        #pragma unroll
        for (int e = 0; e < NEXP; e++) z += expf(l[e] - m);
        float p1 = expf(l[i1] - m) / z;
        float p2 = expf(l[i2] - m) / z;
        float t = expf(p2 - p1);
        g_topk_idx[n * 2 + 0] = i1;
        g_topk_idx[n * 2 + 1] = i2;
        g_topk_w[n * 2 + 0] = 1.f / (1.f + t);
        g_topk_w[n * 2 + 1] = t / (1.f + t);
        atomicAdd(&g_count[i1], 1);
        atomicAdd(&g_count[i2], 1);
    }
}

// ---------------- kernel: scan + tile table ----------------
__global__ void scan_kernel() {
    if (threadIdx.x == 0) {
        int s = 0, nt = 0;
        for (int e = 0; e < NEXP; e++) {
            g_offset[e] = s;
            int c = g_count[e];
            for (int i = 0; i < c; i += TILE_M) {
                g_tile_rbase[nt] = s + i;
                g_tile_rows[nt] = min(c - i, TILE_M);
                g_tile_e[nt] = e;
                nt++;
            }
            s += c;
        }
        g_n_tiles = nt;
    }
}

// ---------------- kernel: scatter ----------------
__global__ void scatter_kernel() {
    int n = blockIdx.x * blockDim.x + threadIdx.x;
    if (n >= N_TOK) return;
    #pragma unroll
    for (int s = 0; s < 2; s++) {
        int e = g_topk_idx[n * 2 + s];
        int pos = atomicAdd(&g_cursor[e], 1);
        int row = g_offset[e] + pos;
        g_list_token[row] = n;
        g_list_w[row] = g_topk_w[n * 2 + s];
        g_pos[n * 2 + s] = row;
    }
}

// ---------------- fp16 mma.sync grouped GEMM ----------------
template <int KD, int NOUT, int PHASE>
__global__ __launch_bounds__(256, 1)
void ffn_kernel(const __half* __restrict__ W, const float* __restrict__ bias) {
    int tile = blockIdx.y;
    if (tile >= g_n_tiles) return;
    int e = g_tile_e[tile];
    int rbase = g_tile_rbase[tile];
    int nrows = g_tile_rows[tile];
    int nbase = blockIdx.x * TILE_N;
    constexpr int T = KD / BK;

    extern __shared__ __align__(1024) char smem[];
    uint32_t sbase = smem_u32(smem);

    int tid = threadIdx.x;
    int lane = tid & 31, wid = tid >> 5;
    int warp_m = wid & 1, warp_n = wid >> 1;

    // ---- producer src/dst precompute ----
    uint32_t adst[2];
    const char* asrc[2];
    #pragma unroll
    for (int j = 0; j < 2; j++) {
        int g = tid + j * 256;
        int r = g >> 2, c = g & 3;
        adst[j] = (uint32_t)(r * 64 + ((c ^ ((r >> 1) & 3)) << 4));
        int rl = (r < nrows) ? r : (nrows - 1);
        int idx = rbase + rl;
        const __half* ap;
        if (PHASE == 1) ap = g_xh + (size_t)g_list_token[idx] * DMODEL;
        else            ap = g_h16 + (size_t)idx * HDIM;
        asrc[j] = (const char*)ap + c * 16;
    }
    uint32_t bdst[4];
    const char* bsrc[4];
    #pragma unroll
    for (int j = 0; j < 4; j++) {
        int g = tid + j * 256;
        int r = g >> 2, c = g & 3;
        bdst[j] = (uint32_t)(A_BYTES + r * 64 + ((c ^ ((r >> 1) & 3)) << 4));
        bsrc[j] = (const char*)(W + ((size_t)e * NOUT + nbase + r) * KD) + c * 16;
    }

    auto issue_tile = [&](int t) {
        uint32_t sb = sbase + (t % STAGES) * STAGE_BYTES;
        size_t koff = (size_t)t * 64;
        #pragma unroll
        for (int j = 0; j < 2; j++) CP_ASYNC16(sb + adst[j], asrc[j] + koff);
        #pragma unroll
        for (int j = 0; j < 4; j++) CP_ASYNC16(sb + bdst[j], bsrc[j] + koff);
    };

    // ---- ldmatrix address precompute ----
    int a_row = warp_m * 64 + (lane & 15);
    int a_hi = (lane >> 4) & 1;
    int a_sw = (a_row >> 1) & 3;
    uint32_t a_base = (uint32_t)(a_row * 64);
    int b_row = warp_n * 64 + (lane & 7) + ((lane & 16) ? 8 : 0);
    int b_hi = (lane >> 3) & 1;
    int b_sw = (b_row >> 1) & 3;
    uint32_t b_base = (uint32_t)(A_BYTES + b_row * 64);

    float acc[4][8][4];
    #pragma unroll
    for (int mi = 0; mi < 4; mi++)
        #pragma unroll
        for (int ni = 0; ni < 8; ni++)
            #pragma unroll
            for (int q = 0; q < 4; q++) acc[mi][ni][q] = 0.f;

    // ---- prologue: fill STAGES-1 stages ----
    #pragma unroll
    for (int t = 0; t < STAGES - 1; t++) { issue_tile(t); CP_COMMIT(); }

    // ---- mainloop: one sync per iter, prefetch first, ks-pipelined frags ----
    for (int t = 0; t < T; t++) {
        CP_WAIT(STAGES - 2);
        __syncthreads();
        if (t + STAGES - 1 < T) issue_tile(t + STAGES - 1);
        CP_COMMIT();

        uint32_t sb = sbase + (t % STAGES) * STAGE_BYTES;
        uint32_t a[2][4][4], b[2][4][4];
        // load ALL fragments for both k16 halves first, then run MMAs:
        // ks0 MMAs overlap ks1 ldmatrix returns.
        #pragma unroll
        for (int ks = 0; ks < 2; ks++) {
            uint32_t ach = (uint32_t)(((ks * 2 + a_hi) ^ a_sw) << 4);
            uint32_t bch = (uint32_t)(((ks * 2 + b_hi) ^ b_sw) << 4);
            #pragma unroll
            for (int mi = 0; mi < 4; mi++)
                LDSM_X4(a[ks][mi][0], a[ks][mi][1], a[ks][mi][2], a[ks][mi][3],
                        sb + a_base + mi * 1024 + ach);
            #pragma unroll
            for (int ni = 0; ni < 4; ni++)
                LDSM_X4(b[ks][ni][0], b[ks][ni][1], b[ks][ni][2], b[ks][ni][3],
                        sb + b_base + ni * 1024 + bch);
        }
        #pragma unroll
        for (int ks = 0; ks < 2; ks++)
            #pragma unroll
            for (int mi = 0; mi < 4; mi++)
                #pragma unroll
                for (int ni = 0; ni < 4; ni++) {
                    MMA16816(acc[mi][2 * ni],     a[ks][mi][0], a[ks][mi][1],
                             a[ks][mi][2], a[ks][mi][3], b[ks][ni][0], b[ks][ni][1]);
                    MMA16816(acc[mi][2 * ni + 1], a[ks][mi][0], a[ks][mi][1],
                             a[ks][mi][2], a[ks][mi][3], b[ks][ni][2], b[ks][ni][3]);
                }
    }

    // ---- epilogue ----
    int r0 = warp_m * 64 + (lane >> 2);
    int cql = (lane & 3) * 2;
    #pragma unroll
    for (int mi = 0; mi < 4; mi++) {
        #pragma unroll
        for (int half = 0; half < 2; half++) {
            int r = r0 + mi * 16 + half * 8;
            if (r < nrows) {
                int rglob = rbase + r;
                if (PHASE == 1) {
                    __half* hp = g_h16 + (size_t)rglob * HDIM + nbase + warp_n * 64 + cql;
                    const float* bp = bias + (size_t)e * NOUT + nbase + warp_n * 64 + cql;
                    #pragma unroll
                    for (int n8 = 0; n8 < 8; n8++) {
                        float v0 = fmaxf(acc[mi][n8][half * 2 + 0] + bp[n8 * 8], 0.f);
                        float v1 = fmaxf(acc[mi][n8][half * 2 + 1] + bp[n8 * 8 + 1], 0.f);
                        *(__half2*)(hp + n8 * 8) = __floats2half2_rn(v0, v1);
                    }
                } else {
                    float wgt = g_list_w[rglob];
                    float* yp = g_ybuf + (size_t)rglob * DMODEL + nbase + warp_n * 64 + cql;
                    const float* bp = bias + (size_t)e * NOUT + nbase + warp_n * 64 + cql;
                    #pragma unroll
                    for (int n8 = 0; n8 < 8; n8++) {
                        float v0 = (acc[mi][n8][half * 2 + 0] + bp[n8 * 8]) * wgt;
                        float v1 = (acc[mi][n8][half * 2 + 1] + bp[n8 * 8 + 1]) * wgt;
                        *(float2*)(yp + n8 * 8) = make_float2(v0, v1);
                    }
                }
            }
        }
    }
}

// ---------------- kernel: residual + LayerNorm ----------------
__device__ __forceinline__ float block_sum(float v, float* red) {
    __syncthreads();
    #pragma unroll
    for (int o = 16; o; o >>= 1) v += __shfl_xor_sync(0xffffffffu, v, o);
    int w = threadIdx.x >> 5, lane = threadIdx.x & 31;
    if (lane == 0) red[w] = v;
    __syncthreads();
    if (w == 0) {
        v = (lane < 8) ? red[lane] : 0.f;
        #pragma unroll
        for (int o = 4; o; o >>= 1) v += __shfl_xor_sync(0xffffffffu, v, o);
        if (lane == 0) red[0] = v;
    }
    __syncthreads();
    return red[0];
}

__global__ void ln_kernel(const float* __restrict__ x, const float* __restrict__ lnw,
                          const float* __restrict__ lnb, float* __restrict__ out) {
    __shared__ float red[32];
    int n = blockIdx.x, tid = threadIdx.x;
    int p0 = g_pos[n * 2 + 0];
    int p1 = g_pos[n * 2 + 1];
    float4 xv = ((const float4*)(x + (size_t)n * DMODEL))[tid];
    float4 a0 = ((const float4*)(&g_ybuf[(size_t)p0 * DMODEL]))[tid];
    float4 a1 = ((const float4*)(&g_ybuf[(size_t)p1 * DMODEL]))[tid];
    float rx = xv.x + a0.x + a1.x, ry = xv.y + a0.y + a1.y;
    float rz = xv.z + a0.z + a1.z, rw = xv.w + a0.w + a1.w;
    float s = block_sum(rx + ry + rz + rw, red);
    float mu = s * (1.f / DMODEL);
    float dx = rx - mu, dy = ry - mu, dz = rz - mu, dw = rw - mu;
    float sq = block_sum(dx * dx + dy * dy + dz * dz + dw * dw, red);
    float inv = rsqrtf(sq * (1.f / DMODEL) + LN_EPS);
    float4 wv = ((const float4*)lnw)[tid];
    float4 bv = ((const float4*)lnb)[tid];
    float4 o = make_float4(dx * inv * wv.x + bv.x, dy * inv * wv.y + bv.y,
                           dz * inv * wv.z + bv.z, dw * inv * wv.w + bv.w);
    ((float4*)(out + (size_t)n * DMODEL))[tid] = o;
}

// ---------------- launch ----------------
extern "C" void kernel_launch(void* const* d_in, const int* in_sizes, int n_in,
                              void* d_out, int out_size) {
    const float* x   = (const float*)d_in[0];
    const float* gw  = (const float*)d_in[1];
    const float* gb  = (const float*)d_in[2];
    const float* w1  = (const float*)d_in[3];
    const float* b1  = (const float*)d_in[4];
    const float* w2  = (const float*)d_in[5];
    const float* b2  = (const float*)d_in[6];
    const float* lnw = (const float*)d_in[7];
    const float* lnb = (const float*)d_in[8];
    float* out = (float*)d_out;

    __half* w1h; cudaGetSymbolAddress((void**)&w1h, g_w1h);
    __half* w2h; cudaGetSymbolAddress((void**)&w2h, g_w2h);

    cudaFuncSetAttribute(ffn_kernel<DMODEL, HDIM, 1>,
                         cudaFuncAttributeMaxDynamicSharedMemorySize, SMEM_DYN);
    cudaFuncSetAttribute(ffn_kernel<HDIM, DMODEL, 2>,
                         cudaFuncAttributeMaxDynamicSharedMemorySize, SMEM_DYN);

    cvtw_kernel<<<2048, 256>>>(w1, w2);
    cvtx_kernel<<<1024, 256>>>(x);
    gate_kernel<<<N_TOK, 256>>>(x, gw, gb);
    scan_kernel<<<1, 32>>>();
    scatter_kernel<<<(N_TOK + 255) / 256, 256>>>();
    ffn_kernel<DMODEL, HDIM, 1><<<dim3(HDIM / TILE_N, MAX_TILES), 256, SMEM_DYN>>>(w1h, b1);
    ffn_kernel<HDIM, DMODEL, 2><<<dim3(DMODEL / TILE_N, MAX_TILES), 256, SMEM_DYN>>>(w2h, b2);
    ln_kernel<<<N_TOK, 256>>>(x, lnw, lnb, out);
}

// round 5
// speedup vs baseline: 2.7651x; 1.1396x over previous
#include <cuda_runtime.h>
#include <cuda_fp16.h>
#include <cstdint>

#define N_TOK 8192
#define DMODEL 1024
#define HDIM 4096
#define NEXP 8
#define LN_EPS 1e-5f
#define TOTALR (N_TOK * 2)

#define TILE_M 128
#define TILE_N 256
#define BK 64
#define STAGES 3
#define A_BYTES 16384           /* 128 rows * 128 B */
#define STAGE_BYTES 49152       /* A 16KB + B 32KB */
#define SMEM_DYN (STAGES * STAGE_BYTES)   /* 147456 */
#define MAX_TILES 136

// ---------------- scratch ----------------
__device__ __half g_w1h[(size_t)NEXP * HDIM * DMODEL];   // 67 MB
__device__ __half g_w2h[(size_t)NEXP * DMODEL * HDIM];   // 67 MB
__device__ __half g_xh[(size_t)N_TOK * DMODEL];          // 16 MB
__device__ __half g_h16[(size_t)TOTALR * HDIM];          // 134 MB
__device__ float  g_ybuf[(size_t)TOTALR * DMODEL];       // 67 MB
__device__ int    g_topk_idx[TOTALR];
__device__ float  g_topk_w[TOTALR];
__device__ int    g_count[NEXP];
__device__ int    g_offset[NEXP];
__device__ int    g_cursor[NEXP];
__device__ int    g_list_token[TOTALR];
__device__ float  g_list_w[TOTALR];
__device__ int    g_pos[TOTALR];
__device__ int    g_tile_rbase[MAX_TILES];
__device__ int    g_tile_rows[MAX_TILES];
__device__ int    g_tile_e[MAX_TILES];
__device__ int    g_n_tiles;

// ---------------- PTX helpers ----------------
__device__ __forceinline__ uint32_t smem_u32(const void* p) {
    uint32_t a;
    asm("{ .reg .u64 t; cvta.to.shared.u64 t, %1; cvt.u32.u64 %0, t; }" : "=r"(a) : "l"(p));
    return a;
}

#define CP_ASYNC16(dst, src) \
    asm volatile("cp.async.cg.shared.global [%0], [%1], 16;" :: "r"((uint32_t)(dst)), "l"(src) : "memory")
#define CP_COMMIT() asm volatile("cp.async.commit_group;" ::: "memory")
#define CP_WAIT(n)  asm volatile("cp.async.wait_group %0;" :: "n"(n) : "memory")

#define LDSM_X4(r0, r1, r2, r3, addr) \
    asm volatile("ldmatrix.sync.aligned.m8n8.x4.shared.b16 {%0,%1,%2,%3}, [%4];" \
        : "=r"(r0), "=r"(r1), "=r"(r2), "=r"(r3) : "r"(addr))

#define MMA16816(c, a0, a1, a2, a3, b0, b1) \
    asm volatile("mma.sync.aligned.m16n8k16.row.col.f32.f16.f16.f32 " \
        "{%0,%1,%2,%3}, {%4,%5,%6,%7}, {%8,%9}, {%0,%1,%2,%3};" \
        : "+f"((c)[0]), "+f"((c)[1]), "+f"((c)[2]), "+f"((c)[3]) \
        : "r"(a0), "r"(a1), "r"(a2), "r"(a3), "r"(b0), "r"(b1))

// ---------------- launch 0: weight convert + routing init ----------------
__global__ void cvtw_kernel(const float* __restrict__ w1, const float* __restrict__ w2) {
    if (blockIdx.x == 0 && threadIdx.x < NEXP) {
        g_count[threadIdx.x] = 0;
        g_cursor[threadIdx.x] = 0;
    }
    const int n4 = NEXP * HDIM * DMODEL / 4;
    int i = blockIdx.x * blockDim.x + threadIdx.x;
    int nth = gridDim.x * blockDim.x;
    for (; i < n4; i += nth) {
        float4 v = ((const float4*)w1)[i];
        ((__half2*)g_w1h)[2 * i]     = __floats2half2_rn(v.x, v.y);
        ((__half2*)g_w1h)[2 * i + 1] = __floats2half2_rn(v.z, v.w);
        float4 u = ((const float4*)w2)[i];
        ((__half2*)g_w2h)[2 * i]     = __floats2half2_rn(u.x, u.y);
        ((__half2*)g_w2h)[2 * i + 1] = __floats2half2_rn(u.z, u.w);
    }
}

// ---------------- launch 1: gating + x->fp16 ----------------
__global__ void gate_kernel(const float* __restrict__ x, const float* __restrict__ gw,
                            const float* __restrict__ gb) {
    __shared__ float xs[DMODEL];
    __shared__ float lg[NEXP];
    int n = blockIdx.x, tid = threadIdx.x;
    float4 xv = ((const float4*)(x + (size_t)n * DMODEL))[tid];
    ((float4*)xs)[tid] = xv;
    // fused x -> fp16
    __half2* xo = (__half2*)(g_xh + (size_t)n * DMODEL) + 2 * tid;
    xo[0] = __floats2half2_rn(xv.x, xv.y);
    xo[1] = __floats2half2_rn(xv.z, xv.w);
    __syncthreads();
    int w = tid >> 5, lane = tid & 31;
    const float* gr = gw + w * DMODEL;
    float s = 0.f;
    #pragma unroll 8
    for (int j = lane; j < DMODEL; j += 32) s += xs[j] * gr[j];
    #pragma unroll
    for (int o = 16; o; o >>= 1) s += __shfl_xor_sync(0xffffffffu, s, o);
    if (lane == 0) lg[w] = s + gb[w];
    __syncthreads();
    if (tid == 0) {
        float l[NEXP];
        #pragma unroll
        for (int e = 0; e < NEXP; e++) l[e] = lg[e];
        int i1 = 0;
        #pragma unroll
        for (int e = 1; e < NEXP; e++) if (l[e] > l[i1]) i1 = e;
        int i2 = (i1 == 0) ? 1 : 0;
        #pragma unroll
        for (int e = 0; e < NEXP; e++) if (e != i1 && l[e] > l[i2]) i2 = e;
        float m = l[0];
        #pragma unroll
        for (int e = 1; e < NEXP; e++) m = fmaxf(m, l[e]);
        float z = 0.f;
        #pragma unroll
        for (int e = 0; e < NEXP; e++) z += expf(l[e] - m);
        float p1 = expf(l[i1] - m) / z;
        float p2 = expf(l[i2] - m) / z;
        float t = expf(p2 - p1);
        g_topk_idx[n * 2 + 0] = i1;
        g_topk_idx[n * 2 + 1] = i2;
        g_topk_w[n * 2 + 0] = 1.f / (1.f + t);
        g_topk_w[n * 2 + 1] = t / (1.f + t);
        atomicAdd(&g_count[i1], 1);
        atomicAdd(&g_count[i2], 1);
    }
}

// ---------------- launch 2: scan + tile table + scatter (single block) ----------------
__global__ void scanscatter_kernel() {
    int tid = threadIdx.x;
    if (tid == 0) {
        int s = 0, nt = 0;
        for (int e = 0; e < NEXP; e++) {
            g_offset[e] = s;
            int c = g_count[e];
            for (int i = 0; i < c; i += TILE_M) {
                g_tile_rbase[nt] = s + i;
                g_tile_rows[nt] = min(c - i, TILE_M);
                g_tile_e[nt] = e;
                nt++;
            }
            s += c;
        }
        g_n_tiles = nt;
    }
    __syncthreads();
    for (int n = tid; n < N_TOK; n += blockDim.x) {
        #pragma unroll
        for (int s = 0; s < 2; s++) {
            int e = g_topk_idx[n * 2 + s];
            int pos = atomicAdd(&g_cursor[e], 1);
            int row = g_offset[e] + pos;
            g_list_token[row] = n;
            g_list_w[row] = g_topk_w[n * 2 + s];
            g_pos[n * 2 + s] = row;
        }
    }
}

// ---------------- launches 3/4: fp16 mma.sync grouped GEMM, BK=64 ----------------
template <int KD, int NOUT, int PHASE>
__global__ __launch_bounds__(256, 1)
void ffn_kernel(const __half* __restrict__ W, const float* __restrict__ bias) {
    int tile = blockIdx.y;
    if (tile >= g_n_tiles) return;
    int e = g_tile_e[tile];
    int rbase = g_tile_rbase[tile];
    int nrows = g_tile_rows[tile];
    int nbase = blockIdx.x * TILE_N;
    constexpr int T = KD / BK;

    extern __shared__ __align__(1024) char smem[];
    uint32_t sbase = smem_u32(smem);

    int tid = threadIdx.x;
    int lane = tid & 31, wid = tid >> 5;
    int warp_m = wid & 1, warp_n = wid >> 1;

    // ---- producer: 128B rows, 8x16B chunks, SW128 swizzle c^(row&7) ----
    int c8 = tid & 7;             // 16B chunk in row
    int rsub = tid >> 3;          // 0..31 row subgroup
    uint32_t pdst0 = (uint32_t)(rsub * 128 + (((c8 ^ (rsub & 7))) << 4));

    const char* asrc[4];          // A rows 32j + rsub (gathered / clamped)
    #pragma unroll
    for (int j = 0; j < 4; j++) {
        int rl = 32 * j + rsub;
        if (rl >= nrows) rl = nrows - 1;
        int idx = rbase + rl;
        const __half* ap;
        if (PHASE == 1) ap = g_xh + (size_t)g_list_token[idx] * DMODEL;
        else            ap = g_h16 + (size_t)idx * HDIM;
        asrc[j] = (const char*)ap + c8 * 16;
    }
    // B rows 32j + rsub, uniform stride: one base pointer
    const char* bsrc = (const char*)(W + ((size_t)e * NOUT + nbase + rsub) * KD) + c8 * 16;

    auto issue_tile = [&](int t) {
        uint32_t sb = sbase + (t % STAGES) * STAGE_BYTES;
        size_t koff = (size_t)t * 128;
        #pragma unroll
        for (int j = 0; j < 4; j++)
            CP_ASYNC16(sb + pdst0 + j * 4096, asrc[j] + koff);
        #pragma unroll
        for (int j = 0; j < 8; j++)
            CP_ASYNC16(sb + A_BYTES + pdst0 + j * 4096, bsrc + koff + (size_t)j * 64 * KD);
    };

    // ---- ldmatrix address precompute ----
    int a_row = warp_m * 64 + (lane & 15);
    int a_hi = (lane >> 4) & 1;
    int a_x = a_row & 7;
    uint32_t a_off = (uint32_t)(a_row * 128);
    int b_row = warp_n * 64 + (lane & 7) + ((lane & 16) ? 8 : 0);
    int b_hi = (lane >> 3) & 1;
    int b_x = b_row & 7;
    uint32_t b_off = (uint32_t)(A_BYTES + b_row * 128);

    float acc[4][8][4];
    #pragma unroll
    for (int mi = 0; mi < 4; mi++)
        #pragma unroll
        for (int ni = 0; ni < 8; ni++)
            #pragma unroll
            for (int q = 0; q < 4; q++) acc[mi][ni][q] = 0.f;

    uint32_t a[2][4][4], b[2][4][4];

    auto ldsm_group = [&](uint32_t sb, int g, int buf) {
        uint32_t ach = (uint32_t)(((2 * g + a_hi) ^ a_x) << 4);
        uint32_t bch = (uint32_t)(((2 * g + b_hi) ^ b_x) << 4);
        #pragma unroll
        for (int mi = 0; mi < 4; mi++)
            LDSM_X4(a[buf][mi][0], a[buf][mi][1], a[buf][mi][2], a[buf][mi][3],
                    sb + a_off + mi * 2048 + ach);
        #pragma unroll
        for (int ni = 0; ni < 4; ni++)
            LDSM_X4(b[buf][ni][0], b[buf][ni][1], b[buf][ni][2], b[buf][ni][3],
                    sb + b_off + ni * 2048 + bch);
    };
    auto mma_group = [&](int buf) {
        #pragma unroll
        for (int mi = 0; mi < 4; mi++)
            #pragma unroll
            for (int ni = 0; ni < 4; ni++) {
                MMA16816(acc[mi][2 * ni],     a[buf][mi][0], a[buf][mi][1],
                         a[buf][mi][2], a[buf][mi][3], b[buf][ni][0], b[buf][ni][1]);
                MMA16816(acc[mi][2 * ni + 1], a[buf][mi][0], a[buf][mi][1],
                         a[buf][mi][2], a[buf][mi][3], b[buf][ni][2], b[buf][ni][3]);
            }
    };

    // ---- prologue: fill STAGES-1 = 2 stages ----
    issue_tile(0); CP_COMMIT();
    issue_tile(1); CP_COMMIT();

    // ---- mainloop: 4 k16-groups per iter, 2-group reg window ----
    for (int t = 0; t < T; t++) {
        CP_WAIT(1);
        __syncthreads();
        if (t + 2 < T) issue_tile(t + 2);
        CP_COMMIT();

        uint32_t sb = sbase + (t % STAGES) * STAGE_BYTES;
        ldsm_group(sb, 0, 0);
        #pragma unroll
        for (int g = 0; g < 4; g++) {
            if (g < 3) ldsm_group(sb, g + 1, (g + 1) & 1);
            mma_group(g & 1);
        }
    }

    // ---- epilogue ----
    int r0 = warp_m * 64 + (lane >> 2);
    int cql = (lane & 3) * 2;
    #pragma unroll
    for (int mi = 0; mi < 4; mi++) {
        #pragma unroll
        for (int half = 0; half < 2; half++) {
            int r = r0 + mi * 16 + half * 8;
            if (r < nrows) {
                int rglob = rbase + r;
                if (PHASE == 1) {
                    __half* hp = g_h16 + (size_t)rglob * HDIM + nbase + warp_n * 64 + cql;
                    const float* bp = bias + (size_t)e * NOUT + nbase + warp_n * 64 + cql;
                    #pragma unroll
                    for (int n8 = 0; n8 < 8; n8++) {
                        float v0 = fmaxf(acc[mi][n8][half * 2 + 0] + bp[n8 * 8], 0.f);
                        float v1 = fmaxf(acc[mi][n8][half * 2 + 1] + bp[n8 * 8 + 1], 0.f);
                        *(__half2*)(hp + n8 * 8) = __floats2half2_rn(v0, v1);
                    }
                } else {
                    float wgt = g_list_w[rglob];
                    float* yp = g_ybuf + (size_t)rglob * DMODEL + nbase + warp_n * 64 + cql;
                    const float* bp = bias + (size_t)e * NOUT + nbase + warp_n * 64 + cql;
                    #pragma unroll
                    for (int n8 = 0; n8 < 8; n8++) {
                        float v0 = (acc[mi][n8][half * 2 + 0] + bp[n8 * 8]) * wgt;
                        float v1 = (acc[mi][n8][half * 2 + 1] + bp[n8 * 8 + 1]) * wgt;
                        *(float2*)(yp + n8 * 8) = make_float2(v0, v1);
                    }
                }
            }
        }
    }
}

// ---------------- launch 5: residual + LayerNorm ----------------
__device__ __forceinline__ float block_sum(float v, float* red) {
    __syncthreads();
    #pragma unroll
    for (int o = 16; o; o >>= 1) v += __shfl_xor_sync(0xffffffffu, v, o);
    int w = threadIdx.x >> 5, lane = threadIdx.x & 31;
    if (lane == 0) red[w] = v;
    __syncthreads();
    if (w == 0) {
        v = (lane < 8) ? red[lane] : 0.f;
        #pragma unroll
        for (int o = 4; o; o >>= 1) v += __shfl_xor_sync(0xffffffffu, v, o);
        if (lane == 0) red[0] = v;
    }
    __syncthreads();
    return red[0];
}

__global__ void ln_kernel(const float* __restrict__ x, const float* __restrict__ lnw,
                          const float* __restrict__ lnb, float* __restrict__ out) {
    __shared__ float red[32];
    int n = blockIdx.x, tid = threadIdx.x;
    int p0 = g_pos[n * 2 + 0];
    int p1 = g_pos[n * 2 + 1];
    float4 xv = ((const float4*)(x + (size_t)n * DMODEL))[tid];
    float4 a0 = ((const float4*)(&g_ybuf[(size_t)p0 * DMODEL]))[tid];
    float4 a1 = ((const float4*)(&g_ybuf[(size_t)p1 * DMODEL]))[tid];
    float rx = xv.x + a0.x + a1.x, ry = xv.y + a0.y + a1.y;
    float rz = xv.z + a0.z + a1.z, rw = xv.w + a0.w + a1.w;
    float s = block_sum(rx + ry + rz + rw, red);
    float mu = s * (1.f / DMODEL);
    float dx = rx - mu, dy = ry - mu, dz = rz - mu, dw = rw - mu;
    float sq = block_sum(dx * dx + dy * dy + dz * dz + dw * dw, red);
    float inv = rsqrtf(sq * (1.f / DMODEL) + LN_EPS);
    float4 wv = ((const float4*)lnw)[tid];
    float4 bv = ((const float4*)lnb)[tid];
    float4 o = make_float4(dx * inv * wv.x + bv.x, dy * inv * wv.y + bv.y,
                           dz * inv * wv.z + bv.z, dw * inv * wv.w + bv.w);
    ((float4*)(out + (size_t)n * DMODEL))[tid] = o;
}

// ---------------- launch ----------------
extern "C" void kernel_launch(void* const* d_in, const int* in_sizes, int n_in,
                              void* d_out, int out_size) {
    const float* x   = (const float*)d_in[0];
    const float* gw  = (const float*)d_in[1];
    const float* gb  = (const float*)d_in[2];
    const float* w1  = (const float*)d_in[3];
    const float* b1  = (const float*)d_in[4];
    const float* w2  = (const float*)d_in[5];
    const float* b2  = (const float*)d_in[6];
    const float* lnw = (const float*)d_in[7];
    const float* lnb = (const float*)d_in[8];
    float* out = (float*)d_out;

    __half* w1h; cudaGetSymbolAddress((void**)&w1h, g_w1h);
    __half* w2h; cudaGetSymbolAddress((void**)&w2h, g_w2h);

    cudaFuncSetAttribute(ffn_kernel<DMODEL, HDIM, 1>,
                         cudaFuncAttributeMaxDynamicSharedMemorySize, SMEM_DYN);
    cudaFuncSetAttribute(ffn_kernel<HDIM, DMODEL, 2>,
                         cudaFuncAttributeMaxDynamicSharedMemorySize, SMEM_DYN);

    cvtw_kernel<<<2048, 256>>>(w1, w2);                                   // 0
    gate_kernel<<<N_TOK, 256>>>(x, gw, gb);                               // 1
    scanscatter_kernel<<<1, 1024>>>();                                    // 2
    ffn_kernel<DMODEL, HDIM, 1><<<dim3(HDIM / TILE_N, MAX_TILES), 256, SMEM_DYN>>>(w1h, b1);  // 3 <- ncu
    ffn_kernel<HDIM, DMODEL, 2><<<dim3(DMODEL / TILE_N, MAX_TILES), 256, SMEM_DYN>>>(w2h, b2);// 4
    ln_kernel<<<N_TOK, 256>>>(x, lnw, lnb, out);                          // 5
}

// round 7
// speedup vs baseline: 3.1342x; 1.1335x over previous
#include <cuda_runtime.h>
#include <cuda_fp16.h>
#include <cstdint>

#define N_TOK 8192
#define DMODEL 1024
#define HDIM 4096
#define NEXP 8
#define LN_EPS 1e-5f
#define TOTALR (N_TOK * 2)

#define TILE_M 128
#define TILE_N 128
#define BK 64
#define STAGES 3
#define A_BYTES 16384           /* 128 rows * 128 B */
#define STAGE_BYTES 32768       /* A 16KB + B 16KB */
#define SMEM_DYN (STAGES * STAGE_BYTES)   /* 98304 */
#define MAX_TILES 136

// ---------------- scratch ----------------
__device__ __half g_w1h[(size_t)NEXP * HDIM * DMODEL];   // 67 MB
__device__ __half g_w2h[(size_t)NEXP * DMODEL * HDIM];   // 67 MB
__device__ __half g_xh[(size_t)N_TOK * DMODEL];          // 16 MB
__device__ __half g_h16[(size_t)TOTALR * HDIM];          // 134 MB
__device__ float  g_ybuf[(size_t)TOTALR * DMODEL];       // 67 MB
__device__ int    g_topk_idx[TOTALR];
__device__ float  g_topk_w[TOTALR];
__device__ int    g_count[NEXP];
__device__ int    g_offset[NEXP];
__device__ int    g_cursor[NEXP];
__device__ int    g_list_token[TOTALR];
__device__ float  g_list_w[TOTALR];
__device__ int    g_pos[TOTALR];
__device__ int    g_tile_rbase[MAX_TILES];
__device__ int    g_tile_rows[MAX_TILES];
__device__ int    g_tile_e[MAX_TILES];
__device__ int    g_n_tiles;

// ---------------- PTX helpers ----------------
__device__ __forceinline__ uint32_t smem_u32(const void* p) {
    uint32_t a;
    asm("{ .reg .u64 t; cvta.to.shared.u64 t, %1; cvt.u32.u64 %0, t; }" : "=r"(a) : "l"(p));
    return a;
}

#define CP_ASYNC16(dst, src) \
    asm volatile("cp.async.cg.shared.global [%0], [%1], 16;" :: "r"((uint32_t)(dst)), "l"(src) : "memory")
#define CP_COMMIT() asm volatile("cp.async.commit_group;" ::: "memory")
#define CP_WAIT(n)  asm volatile("cp.async.wait_group %0;" :: "n"(n) : "memory")

#define LDSM_X4(r0, r1, r2, r3, addr) \
    asm volatile("ldmatrix.sync.aligned.m8n8.x4.shared.b16 {%0,%1,%2,%3}, [%4];" \
        : "=r"(r0), "=r"(r1), "=r"(r2), "=r"(r3) : "r"(addr))

#define MMA16816(c, a0, a1, a2, a3, b0, b1) \
    asm volatile("mma.sync.aligned.m16n8k16.row.col.f32.f16.f16.f32 " \
        "{%0,%1,%2,%3}, {%4,%5,%6,%7}, {%8,%9}, {%0,%1,%2,%3};" \
        : "+f"((c)[0]), "+f"((c)[1]), "+f"((c)[2]), "+f"((c)[3]) \
        : "r"(a0), "r"(a1), "r"(a2), "r"(a3), "r"(b0), "r"(b1))

// ---------------- launch 0: weight convert + routing init ----------------
__global__ void cvtw_kernel(const float* __restrict__ w1, const float* __restrict__ w2) {
    if (blockIdx.x == 0 && threadIdx.x < NEXP) {
        g_count[threadIdx.x] = 0;
        g_cursor[threadIdx.x] = 0;
    }
    const int n4 = NEXP * HDIM * DMODEL / 4;
    int i = blockIdx.x * blockDim.x + threadIdx.x;
    int nth = gridDim.x * blockDim.x;
    for (; i < n4; i += nth) {
        float4 v = ((const float4*)w1)[i];
        ((__half2*)g_w1h)[2 * i]     = __floats2half2_rn(v.x, v.y);
        ((__half2*)g_w1h)[2 * i + 1] = __floats2half2_rn(v.z, v.w);
        float4 u = ((const float4*)w2)[i];
        ((__half2*)g_w2h)[2 * i]     = __floats2half2_rn(u.x, u.y);
        ((__half2*)g_w2h)[2 * i + 1] = __floats2half2_rn(u.z, u.w);
    }
}

// ---------------- launch 1: gating + x->fp16 ----------------
__global__ void gate_kernel(const float* __restrict__ x, const float* __restrict__ gw,
                            const float* __restrict__ gb) {
    __shared__ float xs[DMODEL];
    __shared__ float lg[NEXP];
    int n = blockIdx.x, tid = threadIdx.x;
    float4 xv = ((const float4*)(x + (size_t)n * DMODEL))[tid];
    ((float4*)xs)[tid] = xv;
    __half2* xo = (__half2*)(g_xh + (size_t)n * DMODEL) + 2 * tid;
    xo[0] = __floats2half2_rn(xv.x, xv.y);
    xo[1] = __floats2half2_rn(xv.z, xv.w);
    __syncthreads();
    int w = tid >> 5, lane = tid & 31;
    const float* gr = gw + w * DMODEL;
    float s = 0.f;
    #pragma unroll 8
    for (int j = lane; j < DMODEL; j += 32) s += xs[j] * gr[j];
    #pragma unroll
    for (int o = 16; o; o >>= 1) s += __shfl_xor_sync(0xffffffffu, s, o);
    if (lane == 0) lg[w] = s + gb[w];
    __syncthreads();
    if (tid == 0) {
        float l[NEXP];
        #pragma unroll
        for (int e = 0; e < NEXP; e++) l[e] = lg[e];
        int i1 = 0;
        #pragma unroll
        for (int e = 1; e < NEXP; e++) if (l[e] > l[i1]) i1 = e;
        int i2 = (i1 == 0) ? 1 : 0;
        #pragma unroll
        for (int e = 0; e < NEXP; e++) if (e != i1 && l[e] > l[i2]) i2 = e;
        float m = l[0];
        #pragma unroll
        for (int e = 1; e < NEXP; e++) m = fmaxf(m, l[e]);
        float z = 0.f;
        #pragma unroll
        for (int e = 0; e < NEXP; e++) z += expf(l[e] - m);
        float p1 = expf(l[i1] - m) / z;
        float p2 = expf(l[i2] - m) / z;
        float t = expf(p2 - p1);
        g_topk_idx[n * 2 + 0] = i1;
        g_topk_idx[n * 2 + 1] = i2;
        g_topk_w[n * 2 + 0] = 1.f / (1.f + t);
        g_topk_w[n * 2 + 1] = t / (1.f + t);
        atomicAdd(&g_count[i1], 1);
        atomicAdd(&g_count[i2], 1);
    }
}

// ---------------- launch 2: scan + tile table + scatter ----------------
__global__ void scanscatter_kernel() {
    int tid = threadIdx.x;
    if (tid == 0) {
        int s = 0, nt = 0;
        for (int e = 0; e < NEXP; e++) {
            g_offset[e] = s;
            int c = g_count[e];
            for (int i = 0; i < c; i += TILE_M) {
                g_tile_rbase[nt] = s + i;
                g_tile_rows[nt] = min(c - i, TILE_M);
                g_tile_e[nt] = e;
                nt++;
            }
            s += c;
        }
        g_n_tiles = nt;
    }
    __syncthreads();
    for (int n = tid; n < N_TOK; n += blockDim.x) {
        #pragma unroll
        for (int s = 0; s < 2; s++) {
            int e = g_topk_idx[n * 2 + s];
            int pos = atomicAdd(&g_cursor[e], 1);
            int row = g_offset[e] + pos;
            g_list_token[row] = n;
            g_list_w[row] = g_topk_w[n * 2 + s];
            g_pos[n * 2 + s] = row;
        }
    }
}

// ---------------- launches 3/4: fp16 mma.sync grouped GEMM, 128x128, 2 CTAs/SM ----------------
template <int KD, int NOUT, int PHASE>
__global__ __launch_bounds__(256, 2)
void ffn_kernel(const __half* __restrict__ W, const float* __restrict__ bias) {
    int tile = blockIdx.y;
    if (tile >= g_n_tiles) return;
    int e = g_tile_e[tile];
    int rbase = g_tile_rbase[tile];
    int nrows = g_tile_rows[tile];
    int nbase = blockIdx.x * TILE_N;
    constexpr int T = KD / BK;

    extern __shared__ __align__(1024) char smem[];
    uint32_t sbase = smem_u32(smem);

    int tid = threadIdx.x;
    int lane = tid & 31, wid = tid >> 5;
    int warp_m = wid & 1;          // 2 x 64 rows
    int warp_n = wid >> 1;         // 4 x 32 cols

    // ---- producer: 128B rows, SW128 swizzle chunk = c ^ (row&7) ----
    int c8 = tid & 7;
    int rsub = tid >> 3;          // 0..31
    uint32_t pdst0 = (uint32_t)(rsub * 128 + ((c8 ^ (rsub & 7)) << 4));

    const char* asrc[4];
    #pragma unroll
    for (int j = 0; j < 4; j++) {
        int rl = 32 * j + rsub;
        if (rl >= nrows) rl = nrows - 1;
        int idx = rbase + rl;
        const __half* ap;
        if (PHASE == 1) ap = g_xh + (size_t)g_list_token[idx] * DMODEL;
        else            ap = g_h16 + (size_t)idx * HDIM;
        asrc[j] = (const char*)ap + c8 * 16;
    }
    const char* bsrc = (const char*)(W + ((size_t)e * NOUT + nbase + rsub) * KD) + c8 * 16;

    auto issue_tile = [&](int t) {
        uint32_t sb = sbase + (t % STAGES) * STAGE_BYTES;
        size_t koff = (size_t)t * 128;
        #pragma unroll
        for (int j = 0; j < 4; j++)
            CP_ASYNC16(sb + pdst0 + j * 4096, asrc[j] + koff);
        #pragma unroll
        for (int j = 0; j < 4; j++)
            CP_ASYNC16(sb + A_BYTES + pdst0 + j * 4096,
                       bsrc + koff + (size_t)j * 32 * KD * sizeof(__half));  /* 32 rows in BYTES */
    };

    // ---- ldmatrix address precompute ----
    int a_row = warp_m * 64 + (lane & 15);
    int a_hi = (lane >> 4) & 1;
    int a_x = a_row & 7;
    uint32_t a_off = (uint32_t)(a_row * 128);
    int b_row = warp_n * 32 + (lane & 7) + ((lane & 16) ? 8 : 0);
    int b_hi = (lane >> 3) & 1;
    int b_x = b_row & 7;
    uint32_t b_off = (uint32_t)(A_BYTES + b_row * 128);

    float acc[4][4][4];
    #pragma unroll
    for (int mi = 0; mi < 4; mi++)
        #pragma unroll
        for (int ni = 0; ni < 4; ni++)
            #pragma unroll
            for (int q = 0; q < 4; q++) acc[mi][ni][q] = 0.f;

    // ---- prologue ----
    issue_tile(0); CP_COMMIT();
    issue_tile(1); CP_COMMIT();

    // ---- mainloop: 4 k16-groups per iter ----
    for (int t = 0; t < T; t++) {
        CP_WAIT(1);
        __syncthreads();
        if (t + 2 < T) issue_tile(t + 2);
        CP_COMMIT();

        uint32_t sb = sbase + (t % STAGES) * STAGE_BYTES;
        #pragma unroll
        for (int g = 0; g < 4; g++) {
            uint32_t ach = (uint32_t)(((2 * g + a_hi) ^ a_x) << 4);
            uint32_t bch = (uint32_t)(((2 * g + b_hi) ^ b_x) << 4);
            uint32_t a[4][4], b[2][4];
            #pragma unroll
            for (int mi = 0; mi < 4; mi++)
                LDSM_X4(a[mi][0], a[mi][1], a[mi][2], a[mi][3],
                        sb + a_off + mi * 2048 + ach);
            #pragma unroll
            for (int ni = 0; ni < 2; ni++)
                LDSM_X4(b[ni][0], b[ni][1], b[ni][2], b[ni][3],
                        sb + b_off + ni * 2048 + bch);
            #pragma unroll
            for (int mi = 0; mi < 4; mi++)
                #pragma unroll
                for (int ni = 0; ni < 2; ni++) {
                    MMA16816(acc[mi][2 * ni],     a[mi][0], a[mi][1], a[mi][2], a[mi][3],
                             b[ni][0], b[ni][1]);
                    MMA16816(acc[mi][2 * ni + 1], a[mi][0], a[mi][1], a[mi][2], a[mi][3],
                             b[ni][2], b[ni][3]);
                }
        }
    }

    // ---- epilogue ----
    int r0 = warp_m * 64 + (lane >> 2);
    int cql = (lane & 3) * 2;
    #pragma unroll
    for (int mi = 0; mi < 4; mi++) {
        #pragma unroll
        for (int half = 0; half < 2; half++) {
            int r = r0 + mi * 16 + half * 8;
            if (r < nrows) {
                int rglob = rbase + r;
                if (PHASE == 1) {
                    __half* hp = g_h16 + (size_t)rglob * HDIM + nbase + warp_n * 32 + cql;
                    const float* bp = bias + (size_t)e * NOUT + nbase + warp_n * 32 + cql;
                    #pragma unroll
                    for (int n8 = 0; n8 < 4; n8++) {
                        float v0 = fmaxf(acc[mi][n8][half * 2 + 0] + bp[n8 * 8], 0.f);
                        float v1 = fmaxf(acc[mi][n8][half * 2 + 1] + bp[n8 * 8 + 1], 0.f);
                        *(__half2*)(hp + n8 * 8) = __floats2half2_rn(v0, v1);
                    }
                } else {
                    float wgt = g_list_w[rglob];
                    float* yp = g_ybuf + (size_t)rglob * DMODEL + nbase + warp_n * 32 + cql;
                    const float* bp = bias + (size_t)e * NOUT + nbase + warp_n * 32 + cql;
                    #pragma unroll
                    for (int n8 = 0; n8 < 4; n8++) {
                        float v0 = (acc[mi][n8][half * 2 + 0] + bp[n8 * 8]) * wgt;
                        float v1 = (acc[mi][n8][half * 2 + 1] + bp[n8 * 8 + 1]) * wgt;
                        *(float2*)(yp + n8 * 8) = make_float2(v0, v1);
                    }
                }
            }
        }
    }
}

// ---------------- launch 5: residual + LayerNorm ----------------
__device__ __forceinline__ float block_sum(float v, float* red) {
    __syncthreads();
    #pragma unroll
    for (int o = 16; o; o >>= 1) v += __shfl_xor_sync(0xffffffffu, v, o);
    int w = threadIdx.x >> 5, lane = threadIdx.x & 31;
    if (lane == 0) red[w] = v;
    __syncthreads();
    if (w == 0) {
        v = (lane < 8) ? red[lane] : 0.f;
        #pragma unroll
        for (int o = 4; o; o >>= 1) v += __shfl_xor_sync(0xffffffffu, v, o);
        if (lane == 0) red[0] = v;
    }
    __syncthreads();
    return red[0];
}

__global__ void ln_kernel(const float* __restrict__ x, const float* __restrict__ lnw,
                          const float* __restrict__ lnb, float* __restrict__ out) {
    __shared__ float red[32];
    int n = blockIdx.x, tid = threadIdx.x;
    int p0 = g_pos[n * 2 + 0];
    int p1 = g_pos[n * 2 + 1];
    float4 xv = ((const float4*)(x + (size_t)n * DMODEL))[tid];
    float4 a0 = ((const float4*)(&g_ybuf[(size_t)p0 * DMODEL]))[tid];
    float4 a1 = ((const float4*)(&g_ybuf[(size_t)p1 * DMODEL]))[tid];
    float rx = xv.x + a0.x + a1.x, ry = xv.y + a0.y + a1.y;
    float rz = xv.z + a0.z + a1.z, rw = xv.w + a0.w + a1.w;
    float s = block_sum(rx + ry + rz + rw, red);
    float mu = s * (1.f / DMODEL);
    float dx = rx - mu, dy = ry - mu, dz = rz - mu, dw = rw - mu;
    float sq = block_sum(dx * dx + dy * dy + dz * dz + dw * dw, red);
    float inv = rsqrtf(sq * (1.f / DMODEL) + LN_EPS);
    float4 wv = ((const float4*)lnw)[tid];
    float4 bv = ((const float4*)lnb)[tid];
    float4 o = make_float4(dx * inv * wv.x + bv.x, dy * inv * wv.y + bv.y,
                           dz * inv * wv.z + bv.z, dw * inv * wv.w + bv.w);
    ((float4*)(out + (size_t)n * DMODEL))[tid] = o;
}

// ---------------- launch ----------------
extern "C" void kernel_launch(void* const* d_in, const int* in_sizes, int n_in,
                              void* d_out, int out_size) {
    const float* x   = (const float*)d_in[0];
    const float* gw  = (const float*)d_in[1];
    const float* gb  = (const float*)d_in[2];
    const float* w1  = (const float*)d_in[3];
    const float* b1  = (const float*)d_in[4];
    const float* w2  = (const float*)d_in[5];
    const float* b2  = (const float*)d_in[6];
    const float* lnw = (const float*)d_in[7];
    const float* lnb = (const float*)d_in[8];
    float* out = (float*)d_out;

    __half* w1h; cudaGetSymbolAddress((void**)&w1h, g_w1h);
    __half* w2h; cudaGetSymbolAddress((void**)&w2h, g_w2h);

    cudaFuncSetAttribute(ffn_kernel<DMODEL, HDIM, 1>,
                         cudaFuncAttributeMaxDynamicSharedMemorySize, SMEM_DYN);
    cudaFuncSetAttribute(ffn_kernel<HDIM, DMODEL, 2>,
                         cudaFuncAttributeMaxDynamicSharedMemorySize, SMEM_DYN);

    cvtw_kernel<<<2048, 256>>>(w1, w2);                                   // 0
    gate_kernel<<<N_TOK, 256>>>(x, gw, gb);                               // 1
    scanscatter_kernel<<<1, 1024>>>();                                    // 2
    ffn_kernel<DMODEL, HDIM, 1><<<dim3(HDIM / TILE_N, MAX_TILES), 256, SMEM_DYN>>>(w1h, b1);  // 3 <- ncu
    ffn_kernel<HDIM, DMODEL, 2><<<dim3(DMODEL / TILE_N, MAX_TILES), 256, SMEM_DYN>>>(w2h, b2);// 4
    ln_kernel<<<N_TOK, 256>>>(x, lnw, lnb, out);                          // 5
}